// round 2
// baseline (speedup 1.0000x reference)
#include <cuda_runtime.h>
#include <math.h>

#define BB 2
#define SS 2048
#define DD 1024
#define HH 16
#define HD 64
#define MT (BB*SS)   // 4096 rows total

// Scratch (allocation-free rule: __device__ globals)
__device__ float g_Q[BB*SS*DD];
__device__ float g_K[BB*SS*DD];
__device__ float g_V[BB*SS*DD];
__device__ float g_A[BB*SS*DD];

// ---------------------------------------------------------------------------
// GEMM: C = A[MT x DD] @ W[DD x DD] + bias ; blockIdx.z selects (W,b,C) set.
// 64x64 block tile, 16-deep K tile, 256 threads, 4x4 microtile per thread.
// ---------------------------------------------------------------------------
__global__ void gemm_bias_kernel(const float* __restrict__ A,
                                 const float* __restrict__ W0, const float* __restrict__ b0, float* __restrict__ C0,
                                 const float* __restrict__ W1, const float* __restrict__ b1, float* __restrict__ C1,
                                 const float* __restrict__ W2, const float* __restrict__ b2, float* __restrict__ C2)
{
    const float* W; const float* bias; float* C;
    if (blockIdx.z == 0)      { W = W0; bias = b0; C = C0; }
    else if (blockIdx.z == 1) { W = W1; bias = b1; C = C1; }
    else                      { W = W2; bias = b2; C = C2; }

    __shared__ float As[16][65];
    __shared__ float Bs[16][65];

    const int tid = threadIdx.x;
    const int tx = tid & 15;
    const int ty = tid >> 4;
    const int m0 = blockIdx.y * 64;
    const int n0 = blockIdx.x * 64;

    float acc[4][4] = {};

    for (int k0 = 0; k0 < DD; k0 += 16) {
        // A tile: 64 rows x 16 k
        #pragma unroll
        for (int idx = tid; idx < 64 * 16; idx += 256) {
            int m = idx >> 4, k = idx & 15;
            As[k][m] = A[(size_t)(m0 + m) * DD + k0 + k];
        }
        // W tile: 16 k x 64 n
        #pragma unroll
        for (int idx = tid; idx < 16 * 64; idx += 256) {
            int k = idx >> 6, n = idx & 63;
            Bs[k][n] = W[(size_t)(k0 + k) * DD + n0 + n];
        }
        __syncthreads();

        #pragma unroll
        for (int k = 0; k < 16; k++) {
            float ra[4], rb[4];
            #pragma unroll
            for (int i = 0; i < 4; i++) ra[i] = As[k][ty * 4 + i];
            #pragma unroll
            for (int j = 0; j < 4; j++) rb[j] = Bs[k][tx * 4 + j];
            #pragma unroll
            for (int i = 0; i < 4; i++)
                #pragma unroll
                for (int j = 0; j < 4; j++)
                    acc[i][j] = fmaf(ra[i], rb[j], acc[i][j]);
        }
        __syncthreads();
    }

    #pragma unroll
    for (int i = 0; i < 4; i++) {
        const int m = m0 + ty * 4 + i;
        #pragma unroll
        for (int j = 0; j < 4; j++) {
            const int n = n0 + tx * 4 + j;
            C[(size_t)m * DD + n] = acc[i][j] + bias[n];
        }
    }
}

// ---------------------------------------------------------------------------
// Flash attention: BM=64 queries x BN=64 keys per chunk, HD=64.
// Online softmax; 256 threads; 4x4 microtile for both QK^T and P@V.
// Grid: (S/64, H, B). Dynamic smem.
// ---------------------------------------------------------------------------
__global__ void attn_kernel(const float* __restrict__ Q,
                            const float* __restrict__ K,
                            const float* __restrict__ V,
                            float* __restrict__ O)
{
    extern __shared__ float sm[];
    float* qs  = sm;              // [d][m] 64x65
    float* ks  = qs  + 64 * 65;   // [d][n] 64x65
    float* vs  = ks  + 64 * 65;   // [n][d] 64x65
    float* st  = vs  + 64 * 65;   // [m][n] 64x65
    float* m_s = st  + 64 * 65;   // 64
    float* l_s = m_s + 64;        // 64
    float* a_s = l_s + 64;        // 64

    const int tid = threadIdx.x;
    const int tx = tid & 15;
    const int ty = tid >> 4;
    const int qt = blockIdx.x;
    const int h  = blockIdx.y;
    const int b  = blockIdx.z;

    const float scale = 0.125f;  // 1/sqrt(64)
    const size_t base = (size_t)b * SS * DD + (size_t)h * HD;

    // Load Q tile (pre-scaled), transposed into [d][m]
    #pragma unroll
    for (int idx = tid; idx < 64 * HD; idx += 256) {
        int m = idx >> 6, d = idx & 63;
        qs[d * 65 + m] = Q[base + (size_t)(qt * 64 + m) * DD + d] * scale;
    }
    if (tid < 64) { m_s[tid] = -1e30f; l_s[tid] = 0.0f; }

    float o[4][4] = {};

    for (int n0g = 0; n0g < SS; n0g += 64) {
        // Load K (transposed [d][n]) and V ([n][d]) chunks
        #pragma unroll
        for (int idx = tid; idx < 64 * HD; idx += 256) {
            int n = idx >> 6, d = idx & 63;
            float kv = K[base + (size_t)(n0g + n) * DD + d];
            float vv = V[base + (size_t)(n0g + n) * DD + d];
            ks[d * 65 + n] = kv;
            vs[n * 65 + d] = vv;
        }
        __syncthreads();

        // S = Q @ K^T  (pre-scaled)
        float acc[4][4] = {};
        #pragma unroll 8
        for (int d = 0; d < HD; d++) {
            float rq[4], rk[4];
            #pragma unroll
            for (int i = 0; i < 4; i++) rq[i] = qs[d * 65 + ty * 4 + i];
            #pragma unroll
            for (int j = 0; j < 4; j++) rk[j] = ks[d * 65 + tx * 4 + j];
            #pragma unroll
            for (int i = 0; i < 4; i++)
                #pragma unroll
                for (int j = 0; j < 4; j++)
                    acc[i][j] = fmaf(rq[i], rk[j], acc[i][j]);
        }
        #pragma unroll
        for (int i = 0; i < 4; i++)
            #pragma unroll
            for (int j = 0; j < 4; j++)
                st[(ty * 4 + i) * 65 + tx * 4 + j] = acc[i][j];
        __syncthreads();

        // Online softmax: 4 threads per row (16 cols each), shfl combine
        {
            const int row = tid >> 2;
            const int q4  = tid & 3;
            float* srow = st + row * 65 + q4 * 16;
            float mx = -1e30f;
            #pragma unroll
            for (int c = 0; c < 16; c++) mx = fmaxf(mx, srow[c]);
            mx = fmaxf(mx, __shfl_xor_sync(0xffffffffu, mx, 1));
            mx = fmaxf(mx, __shfl_xor_sync(0xffffffffu, mx, 2));
            const float m_old = m_s[row];
            const float m_new = fmaxf(m_old, mx);
            float sum = 0.0f;
            #pragma unroll
            for (int c = 0; c < 16; c++) {
                float p = __expf(srow[c] - m_new);
                srow[c] = p;
                sum += p;
            }
            sum += __shfl_xor_sync(0xffffffffu, sum, 1);
            sum += __shfl_xor_sync(0xffffffffu, sum, 2);
            if (q4 == 0) {
                const float alpha = __expf(m_old - m_new);
                m_s[row] = m_new;
                l_s[row] = l_s[row] * alpha + sum;
                a_s[row] = alpha;
            }
        }
        __syncthreads();

        // Rescale O and accumulate P @ V
        float ral[4];
        #pragma unroll
        for (int i = 0; i < 4; i++) ral[i] = a_s[ty * 4 + i];
        #pragma unroll
        for (int i = 0; i < 4; i++)
            #pragma unroll
            for (int j = 0; j < 4; j++)
                o[i][j] *= ral[i];

        #pragma unroll 8
        for (int n = 0; n < 64; n++) {
            float rp[4], rv[4];
            #pragma unroll
            for (int i = 0; i < 4; i++) rp[i] = st[(ty * 4 + i) * 65 + n];
            #pragma unroll
            for (int j = 0; j < 4; j++) rv[j] = vs[n * 65 + tx * 4 + j];
            #pragma unroll
            for (int i = 0; i < 4; i++)
                #pragma unroll
                for (int j = 0; j < 4; j++)
                    o[i][j] = fmaf(rp[i], rv[j], o[i][j]);
        }
        __syncthreads();
    }

    // Normalize and write concat layout [B,S,D]
    #pragma unroll
    for (int i = 0; i < 4; i++) {
        const float inv = 1.0f / l_s[ty * 4 + i];
        const int m = qt * 64 + ty * 4 + i;
        #pragma unroll
        for (int j = 0; j < 4; j++)
            O[base + (size_t)m * DD + tx * 4 + j] = o[i][j] * inv;
    }
}

// ---------------------------------------------------------------------------
extern "C" void kernel_launch(void* const* d_in, const int* in_sizes, int n_in,
                              void* d_out, int out_size)
{
    const float* X  = (const float*)d_in[0];
    const float* Wq = (const float*)d_in[1];
    const float* bq = (const float*)d_in[2];
    const float* Wk = (const float*)d_in[3];
    const float* bk = (const float*)d_in[4];
    const float* Wv = (const float*)d_in[5];
    const float* bv = (const float*)d_in[6];
    const float* Wo = (const float*)d_in[7];
    const float* bo = (const float*)d_in[8];
    float* out = (float*)d_out;

    float *Qp, *Kp, *Vp, *Ap;
    cudaGetSymbolAddress((void**)&Qp, g_Q);
    cudaGetSymbolAddress((void**)&Kp, g_K);
    cudaGetSymbolAddress((void**)&Vp, g_V);
    cudaGetSymbolAddress((void**)&Ap, g_A);

    const int attn_smem = (4 * 64 * 65 + 3 * 64) * (int)sizeof(float);  // 67328 B
    static bool attr_set = false;
    if (!attr_set) {
        cudaFuncSetAttribute(attn_kernel, cudaFuncAttributeMaxDynamicSharedMemorySize, attn_smem);
        attr_set = true;
    }

    dim3 blk(256);

    // QKV projections
    dim3 g_qkv(DD / 64, MT / 64, 3);
    gemm_bias_kernel<<<g_qkv, blk>>>(X,
                                     Wq, bq, Qp,
                                     Wk, bk, Kp,
                                     Wv, bv, Vp);

    // Attention
    dim3 g_attn(SS / 64, HH, BB);
    attn_kernel<<<g_attn, blk, attn_smem>>>(Qp, Kp, Vp, Ap);

    // Output projection
    dim3 g_out(DD / 64, MT / 64, 1);
    gemm_bias_kernel<<<g_out, blk>>>(Ap,
                                     Wo, bo, out,
                                     Wo, bo, out,
                                     Wo, bo, out);
}

// round 4
// speedup vs baseline: 2.3688x; 2.3688x over previous
#include <cuda_runtime.h>
#include <math.h>
#include <cstdint>

#define BB 2
#define SS 2048
#define DD 1024
#define HH 16
#define HD 64
#define MT (BB*SS)   // 4096 rows

// Scratch (__device__ globals; no allocs allowed)
__device__ float g_Xh[MT*DD];
__device__ float g_Xl[MT*DD];
__device__ float g_Wth[4*DD*DD];   // [z][N][K] transposed weights, tf32-hi
__device__ float g_Wtl[4*DD*DD];   // tf32-lo
__device__ float g_Q [MT*DD];
__device__ float g_K [MT*DD];
__device__ float g_V [MT*DD];
__device__ float g_Ah[MT*DD];      // attention out, tf32-hi
__device__ float g_Al[MT*DD];      // tf32-lo

// ---------------------------------------------------------------------------
__device__ __forceinline__ uint32_t rna_tf32(float x) {
    uint32_t r;
    asm("cvt.rna.tf32.f32 %0, %1;" : "=r"(r) : "f"(x));
    return r;
}
__device__ __forceinline__ float rna_tf32_f(float x) {
    return __uint_as_float(rna_tf32(x));
}
__device__ __forceinline__ void cpasync16(uint32_t saddr, const void* g) {
    asm volatile("cp.async.cg.shared.global [%0], [%1], 16;" :: "r"(saddr), "l"(g));
}
__device__ __forceinline__ uint32_t smem_u32(const void* p) {
    uint32_t a;
    asm("{ .reg .u64 t; cvta.to.shared.u64 t, %1; cvt.u32.u64 %0, t; }" : "=r"(a) : "l"(p));
    return a;
}
// m16n8k8 tf32 mma: C += A*B
__device__ __forceinline__ void mma8(float c[4], uint32_t a0, uint32_t a1, uint32_t a2, uint32_t a3,
                                     uint32_t b0, uint32_t b1) {
    asm volatile(
        "mma.sync.aligned.m16n8k8.row.col.f32.tf32.tf32.f32 "
        "{%0,%1,%2,%3}, {%4,%5,%6,%7}, {%8,%9}, {%0,%1,%2,%3};"
        : "+f"(c[0]), "+f"(c[1]), "+f"(c[2]), "+f"(c[3])
        : "r"(a0), "r"(a1), "r"(a2), "r"(a3), "r"(b0), "r"(b1));
}

// ---------------------------------------------------------------------------
// Pre-passes
// ---------------------------------------------------------------------------
__global__ void convert_x_kernel(const float* __restrict__ X,
                                 float* __restrict__ Xh, float* __restrict__ Xl) {
    int i = blockIdx.x * blockDim.x + threadIdx.x;
    float4 v = ((const float4*)X)[i];
    float4 h, l;
    h.x = rna_tf32_f(v.x); l.x = rna_tf32_f(v.x - h.x);
    h.y = rna_tf32_f(v.y); l.y = rna_tf32_f(v.y - h.y);
    h.z = rna_tf32_f(v.z); l.z = rna_tf32_f(v.z - h.z);
    h.w = rna_tf32_f(v.w); l.w = rna_tf32_f(v.w - h.w);
    ((float4*)Xh)[i] = h;
    ((float4*)Xl)[i] = l;
}

__global__ void transpose_w_kernel(const float* __restrict__ W0, const float* __restrict__ W1,
                                   const float* __restrict__ W2, const float* __restrict__ W3,
                                   float* __restrict__ Wh, float* __restrict__ Wl) {
    __shared__ float tile[32][33];
    const float* W;
    if (blockIdx.z == 0) W = W0; else if (blockIdx.z == 1) W = W1;
    else if (blockIdx.z == 2) W = W2; else W = W3;
    float* Oh = Wh + (size_t)blockIdx.z * DD * DD;
    float* Ol = Wl + (size_t)blockIdx.z * DD * DD;

    int x = blockIdx.x * 32 + threadIdx.x;   // n
    int y = blockIdx.y * 32;                 // k base
    #pragma unroll
    for (int i = threadIdx.y; i < 32; i += 8)
        tile[i][threadIdx.x] = W[(size_t)(y + i) * DD + x];
    __syncthreads();
    int n = blockIdx.x * 32;
    #pragma unroll
    for (int i = threadIdx.y; i < 32; i += 8) {
        float v = tile[threadIdx.x][i];
        float h = rna_tf32_f(v);
        Oh[(size_t)(n + i) * DD + y + threadIdx.x] = h;
        Ol[(size_t)(n + i) * DD + y + threadIdx.x] = rna_tf32_f(v - h);
    }
}

// ---------------------------------------------------------------------------
// 3xTF32 GEMM via mma.sync: C[z] = A @ W[z]^T + bias[z]
// A given split (Ah,Al) [MT x DD]; W stored [N][K] split.
// CTA 128x128, 256 thr (8 warps, 2x4; warptile 64x32), KC=32 double buffered.
// ---------------------------------------------------------------------------
#define KC 32
#define KT (DD/KC)
#define ASTR 36                       // padded row stride (floats)
#define TILE_F (128*ASTR)             // 4608 floats per matrix tile
#define STAGE_F (4*TILE_F)            // Ah, Al, Bh, Bl
#define GEMM_SMEM (2*STAGE_F*4)       // bytes = 147456

__global__ void __launch_bounds__(256, 1)
gemm3x_kernel(const float* __restrict__ Ah, const float* __restrict__ Al,
              const float* __restrict__ Wth, const float* __restrict__ Wtl,
              const float* __restrict__ b0, const float* __restrict__ b1, const float* __restrict__ b2,
              float* __restrict__ C0, float* __restrict__ C1, float* __restrict__ C2)
{
    extern __shared__ float smf[];
    const uint32_t sbase = smem_u32(smf);
    const int tid = threadIdx.x;
    const int wid = tid >> 5;
    const int lane = tid & 31;
    const int g = lane >> 2;       // groupID
    const int t = lane & 3;        // thread-in-group
    const int wm = wid >> 2;       // 0..1 -> m offset wm*64
    const int wn = wid & 3;        // 0..3 -> n offset wn*32
    const int n0 = blockIdx.x * 128;
    const int m0 = blockIdx.y * 128;

    const float* Bh = Wth + (size_t)blockIdx.z * DD * DD;
    const float* Bl = Wtl + (size_t)blockIdx.z * DD * DD;
    const float* bias; float* C;
    if (blockIdx.z == 0)      { bias = b0; C = C0; }
    else if (blockIdx.z == 1) { bias = b1; C = C1; }
    else                      { bias = b2; C = C2; }

    float c[4][4][4];
    #pragma unroll
    for (int i = 0; i < 4; i++)
        #pragma unroll
        for (int j = 0; j < 4; j++)
            #pragma unroll
            for (int q = 0; q < 4; q++) c[i][j][q] = 0.0f;

    auto load_stage = [&](int kt, int s) {
        const float* srcs[4] = {
            Ah + (size_t)m0 * DD + kt * KC,
            Al + (size_t)m0 * DD + kt * KC,
            Bh + (size_t)n0 * DD + kt * KC,
            Bl + (size_t)n0 * DD + kt * KC };
        #pragma unroll
        for (int mat = 0; mat < 4; mat++) {
            uint32_t dst = sbase + (uint32_t)((s * STAGE_F + mat * TILE_F) * 4);
            const float* src = srcs[mat];
            #pragma unroll
            for (int i = 0; i < 4; i++) {
                int idx = tid + i * 256;          // 1024 chunks
                int row = idx >> 3, j = idx & 7;
                cpasync16(dst + (uint32_t)((row * ASTR + j * 4) * 4),
                          src + (size_t)row * DD + j * 4);
            }
        }
    };

    load_stage(0, 0);
    asm volatile("cp.async.commit_group;" ::: "memory");

    for (int kt = 0; kt < KT; kt++) {
        const int s = kt & 1;
        if (kt + 1 < KT) {
            load_stage(kt + 1, s ^ 1);
            asm volatile("cp.async.commit_group;" ::: "memory");
            asm volatile("cp.async.wait_group 1;" ::: "memory");
        } else {
            asm volatile("cp.async.wait_group 0;" ::: "memory");
        }
        __syncthreads();

        const float* sAh = smf + s * STAGE_F;
        const float* sAl = sAh + TILE_F;
        const float* sBh = sAl + TILE_F;
        const float* sBl = sBh + TILE_F;

        #pragma unroll
        for (int kk = 0; kk < KC / 8; kk++) {
            const int kc = kk * 8;
            uint32_t ah[4][4], al[4][4], bh[4][2], bl[4][2];
            #pragma unroll
            for (int mt = 0; mt < 4; mt++) {
                const int r = wm * 64 + mt * 16 + g;
                ah[mt][0] = __float_as_uint(sAh[r * ASTR + kc + t]);
                ah[mt][1] = __float_as_uint(sAh[(r + 8) * ASTR + kc + t]);
                ah[mt][2] = __float_as_uint(sAh[r * ASTR + kc + t + 4]);
                ah[mt][3] = __float_as_uint(sAh[(r + 8) * ASTR + kc + t + 4]);
                al[mt][0] = __float_as_uint(sAl[r * ASTR + kc + t]);
                al[mt][1] = __float_as_uint(sAl[(r + 8) * ASTR + kc + t]);
                al[mt][2] = __float_as_uint(sAl[r * ASTR + kc + t + 4]);
                al[mt][3] = __float_as_uint(sAl[(r + 8) * ASTR + kc + t + 4]);
            }
            #pragma unroll
            for (int nt = 0; nt < 4; nt++) {
                const int nn = wn * 32 + nt * 8 + g;
                bh[nt][0] = __float_as_uint(sBh[nn * ASTR + kc + t]);
                bh[nt][1] = __float_as_uint(sBh[nn * ASTR + kc + t + 4]);
                bl[nt][0] = __float_as_uint(sBl[nn * ASTR + kc + t]);
                bl[nt][1] = __float_as_uint(sBl[nn * ASTR + kc + t + 4]);
            }
            #pragma unroll
            for (int mt = 0; mt < 4; mt++)
                #pragma unroll
                for (int nt = 0; nt < 4; nt++) {
                    mma8(c[mt][nt], al[mt][0], al[mt][1], al[mt][2], al[mt][3], bh[nt][0], bh[nt][1]);
                    mma8(c[mt][nt], ah[mt][0], ah[mt][1], ah[mt][2], ah[mt][3], bl[nt][0], bl[nt][1]);
                    mma8(c[mt][nt], ah[mt][0], ah[mt][1], ah[mt][2], ah[mt][3], bh[nt][0], bh[nt][1]);
                }
        }
        __syncthreads();
    }

    // Epilogue: direct float2 stores
    #pragma unroll
    for (int mt = 0; mt < 4; mt++) {
        const int r0 = m0 + wm * 64 + mt * 16 + g;
        #pragma unroll
        for (int nt = 0; nt < 4; nt++) {
            const int cc = n0 + wn * 32 + nt * 8 + t * 2;
            const float bx = bias[cc], by = bias[cc + 1];
            float2 v0 = { c[mt][nt][0] + bx, c[mt][nt][1] + by };
            float2 v1 = { c[mt][nt][2] + bx, c[mt][nt][3] + by };
            *(float2*)&C[(size_t)r0 * DD + cc] = v0;
            *(float2*)&C[(size_t)(r0 + 8) * DD + cc] = v1;
        }
    }
}

// ---------------------------------------------------------------------------
// Flash attention with mma.sync tf32.
// Block: 64 queries, 128 thr (4 warps; warp w owns rows w*16..w*16+15).
// Writes tf32 hi/lo split output for the 3xTF32 out-projection.
// ---------------------------------------------------------------------------
#define QSTR 68
#define VSTR 72
#define ATTN_SMEM ((64*QSTR*3 + 64*VSTR + 192) * 4)

__global__ void __launch_bounds__(128, 1)
attn_kernel(const float* __restrict__ Q,
            const float* __restrict__ K,
            const float* __restrict__ V,
            float* __restrict__ Oh, float* __restrict__ Ol)
{
    extern __shared__ float sm[];
    float* qs  = sm;                  // [64][QSTR]
    float* ks  = qs + 64 * QSTR;      // [64][QSTR]  (key-major, d contiguous)
    float* st  = ks + 64 * QSTR;      // [64][QSTR]  scores/P
    float* vs  = st + 64 * QSTR;      // [64][VSTR]  (key-major, d contiguous)
    float* m_s = vs + 64 * VSTR;
    float* l_s = m_s + 64;
    float* a_s = l_s + 64;

    const int tid = threadIdx.x;
    const int wid = tid >> 5;
    const int lane = tid & 31;
    const int g = lane >> 2;
    const int t = lane & 3;
    const int qt = blockIdx.x;
    const int h  = blockIdx.y;
    const int b  = blockIdx.z;
    const size_t base = (size_t)b * SS * DD + (size_t)h * HD;

    // Load Q (pre-scaled, tf32-rounded)
    #pragma unroll
    for (int i = 0; i < 8; i++) {
        int idx = tid + i * 128;            // 1024 float4s
        int m = idx >> 4, d4 = (idx & 15) * 4;
        float4 v = *(const float4*)&Q[base + (size_t)(qt * 64 + m) * DD + d4];
        qs[m * QSTR + d4 + 0] = rna_tf32_f(v.x * 0.125f);
        qs[m * QSTR + d4 + 1] = rna_tf32_f(v.y * 0.125f);
        qs[m * QSTR + d4 + 2] = rna_tf32_f(v.z * 0.125f);
        qs[m * QSTR + d4 + 3] = rna_tf32_f(v.w * 0.125f);
    }
    if (tid < 64) { m_s[tid] = -1e30f; l_s[tid] = 0.0f; }

    float o[8][4];
    #pragma unroll
    for (int nt = 0; nt < 8; nt++)
        #pragma unroll
        for (int q = 0; q < 4; q++) o[nt][q] = 0.0f;

    const int mrow = wid * 16;   // warp's row base

    for (int n0g = 0; n0g < SS; n0g += 64) {
        __syncthreads();   // prior PV reads of st/vs complete
        #pragma unroll
        for (int i = 0; i < 8; i++) {
            int idx = tid + i * 128;
            int n = idx >> 4, d4 = (idx & 15) * 4;
            float4 kv = *(const float4*)&K[base + (size_t)(n0g + n) * DD + d4];
            float4 vv = *(const float4*)&V[base + (size_t)(n0g + n) * DD + d4];
            ks[n * QSTR + d4 + 0] = rna_tf32_f(kv.x);
            ks[n * QSTR + d4 + 1] = rna_tf32_f(kv.y);
            ks[n * QSTR + d4 + 2] = rna_tf32_f(kv.z);
            ks[n * QSTR + d4 + 3] = rna_tf32_f(kv.w);
            vs[n * VSTR + d4 + 0] = rna_tf32_f(vv.x);
            vs[n * VSTR + d4 + 1] = rna_tf32_f(vv.y);
            vs[n * VSTR + d4 + 2] = rna_tf32_f(vv.z);
            vs[n * VSTR + d4 + 3] = rna_tf32_f(vv.w);
        }
        __syncthreads();

        // S = Q @ K^T  (warp: 16 rows x 64 cols)
        float s[8][4];
        #pragma unroll
        for (int nt = 0; nt < 8; nt++)
            #pragma unroll
            for (int q = 0; q < 4; q++) s[nt][q] = 0.0f;

        #pragma unroll
        for (int kk = 0; kk < 8; kk++) {
            const int kc = kk * 8;
            uint32_t a0 = __float_as_uint(qs[(mrow + g) * QSTR + kc + t]);
            uint32_t a1 = __float_as_uint(qs[(mrow + g + 8) * QSTR + kc + t]);
            uint32_t a2 = __float_as_uint(qs[(mrow + g) * QSTR + kc + t + 4]);
            uint32_t a3 = __float_as_uint(qs[(mrow + g + 8) * QSTR + kc + t + 4]);
            #pragma unroll
            for (int nt = 0; nt < 8; nt++) {
                uint32_t b0 = __float_as_uint(ks[(nt * 8 + g) * QSTR + kc + t]);
                uint32_t b1 = __float_as_uint(ks[(nt * 8 + g) * QSTR + kc + t + 4]);
                mma8(s[nt], a0, a1, a2, a3, b0, b1);
            }
        }
        // write S to smem
        #pragma unroll
        for (int nt = 0; nt < 8; nt++) {
            *(float2*)&st[(mrow + g) * QSTR + nt * 8 + t * 2]     = make_float2(s[nt][0], s[nt][1]);
            *(float2*)&st[(mrow + g + 8) * QSTR + nt * 8 + t * 2] = make_float2(s[nt][2], s[nt][3]);
        }
        __syncthreads();

        // online softmax: 2 threads per row
        {
            const int row = tid >> 1;
            const int half = tid & 1;
            float* srow = st + row * QSTR + half * 32;
            float mx = -1e30f;
            #pragma unroll
            for (int cdx = 0; cdx < 32; cdx++) mx = fmaxf(mx, srow[cdx]);
            mx = fmaxf(mx, __shfl_xor_sync(0xffffffffu, mx, 1));
            const float m_old = m_s[row];
            const float m_new = fmaxf(m_old, mx);
            float sum = 0.0f;
            #pragma unroll
            for (int cdx = 0; cdx < 32; cdx++) {
                float p = rna_tf32_f(__expf(srow[cdx] - m_new));
                srow[cdx] = p;
                sum += p;
            }
            sum += __shfl_xor_sync(0xffffffffu, sum, 1);
            if (half == 0) {
                const float alpha = __expf(m_old - m_new);
                m_s[row] = m_new;
                l_s[row] = l_s[row] * alpha + sum;
                a_s[row] = alpha;
            }
        }
        __syncthreads();

        // rescale O, then O += P @ V
        const float al0 = a_s[mrow + g];
        const float al1 = a_s[mrow + g + 8];
        #pragma unroll
        for (int nt = 0; nt < 8; nt++) {
            o[nt][0] *= al0; o[nt][1] *= al0;
            o[nt][2] *= al1; o[nt][3] *= al1;
        }
        #pragma unroll
        for (int kk = 0; kk < 8; kk++) {
            const int kc = kk * 8;
            uint32_t a0 = __float_as_uint(st[(mrow + g) * QSTR + kc + t]);
            uint32_t a1 = __float_as_uint(st[(mrow + g + 8) * QSTR + kc + t]);
            uint32_t a2 = __float_as_uint(st[(mrow + g) * QSTR + kc + t + 4]);
            uint32_t a3 = __float_as_uint(st[(mrow + g + 8) * QSTR + kc + t + 4]);
            #pragma unroll
            for (int nt = 0; nt < 8; nt++) {
                uint32_t b0 = __float_as_uint(vs[(kc + t) * VSTR + nt * 8 + g]);
                uint32_t b1 = __float_as_uint(vs[(kc + t + 4) * VSTR + nt * 8 + g]);
                mma8(o[nt], a0, a1, a2, a3, b0, b1);
            }
        }
    }
    __syncthreads();

    // normalize + split hi/lo store (concat layout)
    const float inv0 = 1.0f / l_s[mrow + g];
    const float inv1 = 1.0f / l_s[mrow + g + 8];
    #pragma unroll
    for (int nt = 0; nt < 8; nt++) {
        const int cc = nt * 8 + t * 2;
        const size_t r0 = base + (size_t)(qt * 64 + mrow + g) * DD + cc;
        const size_t r1 = base + (size_t)(qt * 64 + mrow + g + 8) * DD + cc;
        float v00 = o[nt][0] * inv0, v01 = o[nt][1] * inv0;
        float v10 = o[nt][2] * inv1, v11 = o[nt][3] * inv1;
        float h00 = rna_tf32_f(v00), h01 = rna_tf32_f(v01);
        float h10 = rna_tf32_f(v10), h11 = rna_tf32_f(v11);
        *(float2*)&Oh[r0] = make_float2(h00, h01);
        *(float2*)&Oh[r1] = make_float2(h10, h11);
        *(float2*)&Ol[r0] = make_float2(rna_tf32_f(v00 - h00), rna_tf32_f(v01 - h01));
        *(float2*)&Ol[r1] = make_float2(rna_tf32_f(v10 - h10), rna_tf32_f(v11 - h11));
    }
}

// ---------------------------------------------------------------------------
extern "C" void kernel_launch(void* const* d_in, const int* in_sizes, int n_in,
                              void* d_out, int out_size)
{
    const float* X  = (const float*)d_in[0];
    const float* Wq = (const float*)d_in[1];
    const float* bq = (const float*)d_in[2];
    const float* Wk = (const float*)d_in[3];
    const float* bk = (const float*)d_in[4];
    const float* Wv = (const float*)d_in[5];
    const float* bv = (const float*)d_in[6];
    const float* Wo = (const float*)d_in[7];
    const float* bo = (const float*)d_in[8];
    float* out = (float*)d_out;

    float *Xh, *Xl, *Wth, *Wtl, *Qp, *Kp, *Vp, *Ahp, *Alp;
    cudaGetSymbolAddress((void**)&Xh,  g_Xh);
    cudaGetSymbolAddress((void**)&Xl,  g_Xl);
    cudaGetSymbolAddress((void**)&Wth, g_Wth);
    cudaGetSymbolAddress((void**)&Wtl, g_Wtl);
    cudaGetSymbolAddress((void**)&Qp,  g_Q);
    cudaGetSymbolAddress((void**)&Kp,  g_K);
    cudaGetSymbolAddress((void**)&Vp,  g_V);
    cudaGetSymbolAddress((void**)&Ahp, g_Ah);
    cudaGetSymbolAddress((void**)&Alp, g_Al);

    static bool attr_set = false;
    if (!attr_set) {
        cudaFuncSetAttribute(gemm3x_kernel, cudaFuncAttributeMaxDynamicSharedMemorySize, GEMM_SMEM);
        cudaFuncSetAttribute(attn_kernel, cudaFuncAttributeMaxDynamicSharedMemorySize, ATTN_SMEM);
        attr_set = true;
    }

    // 1) split X
    convert_x_kernel<<<MT * DD / 4 / 256, 256>>>(X, Xh, Xl);

    // 2) transpose + split weights
    dim3 tg(DD / 32, DD / 32, 4);
    transpose_w_kernel<<<tg, dim3(32, 8)>>>(Wq, Wk, Wv, Wo, Wth, Wtl);

    // 3) QKV projections
    dim3 g_qkv(DD / 128, MT / 128, 3);
    gemm3x_kernel<<<g_qkv, 256, GEMM_SMEM>>>(Xh, Xl, Wth, Wtl,
                                             bq, bk, bv, Qp, Kp, Vp);

    // 4) attention
    dim3 g_attn(SS / 64, HH, BB);
    attn_kernel<<<g_attn, 128, ATTN_SMEM>>>(Qp, Kp, Vp, Ahp, Alp);

    // 5) output projection
    dim3 g_out(DD / 128, MT / 128, 1);
    gemm3x_kernel<<<g_out, 256, GEMM_SMEM>>>(Ahp, Alp,
                                             Wth + 3 * (size_t)DD * DD, Wtl + 3 * (size_t)DD * DD,
                                             bo, bo, bo, out, out, out);
}